// round 1
// baseline (speedup 1.0000x reference)
#include <cuda_runtime.h>

// Problem dims
#define V_ 32000
#define E_ 1024
#define H_ 1024
#define B_ 32
#define T_ 128
#define M_ (B_ * T_)          // 4096 rows of the flattened sequence

// Output layout in d_out (outputs concatenated in tuple order)
#define OUT_PROB 0
#define OUT_HID  ((size_t)M_ * V_)                 // 131,072,000
#define OUT_LAST (OUT_HID + 2ULL * B_ * H_)        // +65,536

typedef unsigned long long ull;

// ---------------- scratch (device globals: allocation-free) ----------------
__device__ float g_bufA[M_ * H_];      // 16 MB: xw (proj output)
__device__ float g_bufB[M_ * H_];      // 16 MB: y (recurrence output)
__device__ float g_hbuf[2][B_ * H_];   // hidden double buffer, layout [b][j]
__device__ ull   g_acnt = 0;           // monotonic arrival counter
__device__ ull   g_gen  = 0;           // monotonic generation (barriers completed)

// ---------------- packed fp32x2 helpers (FFMA2: 2x fp32 FMA rate) ---------
__device__ __forceinline__ void ffma2(ull& c, ull a, ull b) {
    asm("fma.rn.f32x2 %0, %1, %2, %0;" : "+l"(c) : "l"(a), "l"(b));
}
__device__ __forceinline__ ull pack2(float x) {
    ull r; asm("mov.b64 %0, {%1, %1};" : "=l"(r) : "f"(x)); return r;
}
__device__ __forceinline__ float2 unpack2(ull v) {
    float2 r; asm("mov.b64 {%0, %1}, %2;" : "=f"(r.x), "=f"(r.y) : "l"(v)); return r;
}

// ============================================================================
// GEMM: C[m][n] = sum_k A[g(m)][k] * Bm[n][k] + bias1[n] (+ bias2[n])
// A row-major [*, K], Bm row-major [N, K], K = 1024 fixed.
// Block tile 128x128, BK=16, 256 threads, 8x8 per thread, smem double-buffered.
// Optional gather: A row index = gather[m] (embedding lookup).
// ============================================================================
#define BK 16
#define TS 132                 // padded smem row stride (floats), 132*4 % 16 == 0
#define GEMM_SMEM (4 * BK * TS * 4)   // 2 bufs x (As + Bs) = 33792 B

__global__ void __launch_bounds__(256, 2) gemm_kernel(
    const float* __restrict__ A, const int* __restrict__ gather,
    const float* __restrict__ Bm, const float* __restrict__ bias1,
    const float* __restrict__ bias2, float* __restrict__ C, int N)
{
    extern __shared__ float sm[];
    const int K = 1024;
    const int tid = threadIdx.x;
    const int n0 = blockIdx.x * 128;
    const int m0 = blockIdx.y * 128;
    const int tx8 = (tid & 15) * 8;
    const int ty8 = (tid >> 4) * 8;

    // loader mapping: 2 threads per row, 8 floats each
    const int lr = tid >> 1;
    const int lk = (tid & 1) * 8;
    const float* arow;
    {
        int m = m0 + lr;
        int ra = gather ? gather[m] : m;
        arow = A + (size_t)ra * K + lk;
    }
    const float* brow = Bm + (size_t)(n0 + lr) * K + lk;

    ull c2[8][4];
    #pragma unroll
    for (int i = 0; i < 8; i++)
        #pragma unroll
        for (int j = 0; j < 4; j++) c2[i][j] = 0ULL;

    // prologue: load + store chunk 0 into buffer 0
    float4 ra0 = *(const float4*)(arow);
    float4 ra1 = *(const float4*)(arow + 4);
    float4 rb0 = *(const float4*)(brow);
    float4 rb1 = *(const float4*)(brow + 4);
    {
        float ta[8], tb[8];
        *(float4*)ta = ra0; *(float4*)(ta + 4) = ra1;
        *(float4*)tb = rb0; *(float4*)(tb + 4) = rb1;
        float* As = sm;
        float* Bs = sm + 2 * BK * TS;
        #pragma unroll
        for (int j = 0; j < 8; j++) {
            As[(lk + j) * TS + lr] = ta[j];
            Bs[(lk + j) * TS + lr] = tb[j];
        }
    }
    __syncthreads();

    const int NC = K / BK;   // 64 chunks
    for (int c = 0; c < NC; c++) {
        // issue next chunk's global loads early
        if (c < NC - 1) {
            const float* ap = arow + (c + 1) * BK;
            const float* bp = brow + (c + 1) * BK;
            ra0 = *(const float4*)(ap);
            ra1 = *(const float4*)(ap + 4);
            rb0 = *(const float4*)(bp);
            rb1 = *(const float4*)(bp + 4);
        }
        // compute current chunk
        {
            const float* As = sm + (c & 1) * BK * TS;
            const float* Bs = sm + 2 * BK * TS + (c & 1) * BK * TS;
            #pragma unroll
            for (int kk = 0; kk < BK; kk++) {
                const float* ar = As + kk * TS + ty8;
                const float* br = Bs + kk * TS + tx8;
                float a[8];
                *(float4*)a       = *(const float4*)ar;
                *(float4*)(a + 4) = *(const float4*)(ar + 4);
                ulonglong2 b01 = *(const ulonglong2*)br;
                ulonglong2 b23 = *(const ulonglong2*)(br + 4);
                ull bl0 = b01.x, bl1 = b01.y, bl2 = b23.x, bl3 = b23.y;
                #pragma unroll
                for (int i = 0; i < 8; i++) {
                    ull av = pack2(a[i]);
                    ffma2(c2[i][0], av, bl0);
                    ffma2(c2[i][1], av, bl1);
                    ffma2(c2[i][2], av, bl2);
                    ffma2(c2[i][3], av, bl3);
                }
            }
        }
        // store next chunk into the other buffer
        if (c < NC - 1) {
            float ta[8], tb[8];
            *(float4*)ta = ra0; *(float4*)(ta + 4) = ra1;
            *(float4*)tb = rb0; *(float4*)(tb + 4) = rb1;
            float* As = sm + ((c + 1) & 1) * BK * TS;
            float* Bs = sm + 2 * BK * TS + ((c + 1) & 1) * BK * TS;
            #pragma unroll
            for (int j = 0; j < 8; j++) {
                As[(lk + j) * TS + lr] = ta[j];
                Bs[(lk + j) * TS + lr] = tb[j];
            }
            __syncthreads();
        }
    }

    // epilogue
    float bb[8];
    #pragma unroll
    for (int j = 0; j < 8; j++) {
        int n = n0 + tx8 + j;
        bb[j] = bias1[n] + (bias2 ? bias2[n] : 0.0f);
    }
    #pragma unroll
    for (int i = 0; i < 8; i++) {
        float o[8];
        #pragma unroll
        for (int j = 0; j < 4; j++) {
            float2 v = unpack2(c2[i][j]);
            o[2 * j]     = v.x + bb[2 * j];
            o[2 * j + 1] = v.y + bb[2 * j + 1];
        }
        size_t off = (size_t)(m0 + ty8 + i) * N + n0 + tx8;
        *(float4*)&C[off]     = *(float4*)o;
        *(float4*)&C[off + 4] = *(float4*)(o + 4);
    }
}

// ============================================================================
// Persistent recurrence: for t in 0..T-1: h = tanh(xw[:,t,:] + h @ Whh^T)
// (biases already folded into xw). 128 blocks x 256 threads, 1 block/SM,
// full h[32][1024] staged in smem each step, grid barrier between steps.
// Block blk owns output rows i in [blk*8, blk*8+8) for all 32 batches.
// ============================================================================
#define NB 128
#define HS 1028                                   // padded smem h stride (floats)
#define REC_SMEM ((32 * HS + 8 * 33 + 2) * 4)

__device__ __forceinline__ void gridbar() {
    __syncthreads();
    if (threadIdx.x == 0) {
        __threadfence();
        ull a = atomicAdd(&g_acnt, 1ULL) + 1ULL;
        ull tgt = (a + NB - 1) / NB;
        if (a == tgt * NB) {
            atomicExch(&g_gen, tgt);              // release
        } else {
            while (*((volatile ull*)&g_gen) < tgt) { __nanosleep(64); }
        }
        __threadfence();
    }
    __syncthreads();
}

__global__ void __launch_bounds__(256, 1) rnn_rec(
    const float* __restrict__ xw,     // [B][T][H]
    const float* __restrict__ Whh,    // [H][H]
    const float* __restrict__ hinit,  // [B][H]
    float* __restrict__ y,            // [B][T][H]
    float* __restrict__ hfin)         // [B][H]
{
    extern __shared__ float sm[];
    float* h_s  = sm;                  // [32][HS]
    float* hn_s = sm + 32 * HS;        // [8][33]

    const int tid = threadIdx.x;
    const int blk = blockIdx.x;
    const int b  = tid & 31;           // compute mapping: warp = one i, lanes = b
    const int il = tid >> 5;
    const int i  = blk * 8 + il;
    const int bb = tid >> 3;           // writer mapping
    const int io = tid & 7;
    const int iw = blk * 8 + io;

    // initialize hidden buffer 0 (this block's slice)
    g_hbuf[0][bb * H_ + iw] = hinit[bb * H_ + iw];
    gridbar();

    const float* wrow = Whh + (size_t)i * H_;

    for (int t = 0; t < T_; t++) {
        const float* hcur = g_hbuf[t & 1];
        // cooperative load of full h into smem (coalesced float4)
        #pragma unroll
        for (int r = 0; r < 32; r++) {
            *(float4*)&h_s[r * HS + tid * 4] = *(const float4*)&hcur[r * H_ + tid * 4];
        }
        __syncthreads();

        ull a0 = 0, a1 = 0, a2 = 0, a3 = 0;
        const float* hb = h_s + b * HS;
        #pragma unroll 4
        for (int j = 0; j < H_; j += 8) {
            ulonglong2 hv0 = *(const ulonglong2*)(hb + j);
            ulonglong2 hv1 = *(const ulonglong2*)(hb + j + 4);
            ulonglong2 wv0 = *(const ulonglong2*)(wrow + j);   // warp-uniform, L1-hot
            ulonglong2 wv1 = *(const ulonglong2*)(wrow + j + 4);
            ffma2(a0, hv0.x, wv0.x);
            ffma2(a1, hv0.y, wv0.y);
            ffma2(a2, hv1.x, wv1.x);
            ffma2(a3, hv1.y, wv1.y);
        }
        float2 f0 = unpack2(a0), f1 = unpack2(a1), f2 = unpack2(a2), f3 = unpack2(a3);
        float dot = ((f0.x + f0.y) + (f1.x + f1.y)) + ((f2.x + f2.y) + (f3.x + f3.y));
        float hv = tanhf(dot + xw[((size_t)b * T_ + t) * H_ + i]);

        hn_s[il * 33 + b] = hv;
        __syncthreads();

        float v = hn_s[io * 33 + bb];
        g_hbuf[(t + 1) & 1][bb * H_ + iw] = v;
        y[((size_t)bb * T_ + t) * H_ + iw] = v;
        if (t == T_ - 1) hfin[bb * H_ + iw] = v;

        gridbar();
    }
}

// last_output[b][v] = output_prob[(b*T + T-1)*V + v]
__global__ void copy_last(const float* __restrict__ prob, float* __restrict__ dst) {
    int idx = blockIdx.x * 256 + threadIdx.x;
    int b = idx / V_;
    int v = idx - b * V_;
    dst[idx] = prob[((size_t)(b * T_ + T_ - 1)) * V_ + v];
}

// ============================================================================
extern "C" void kernel_launch(void* const* d_in, const int* in_sizes, int n_in,
                              void* d_out, int out_size)
{
    const int*   tok  = (const int*)  d_in[0];
    const float* hid  = (const float*)d_in[1];
    const float* emb  = (const float*)d_in[2];
    const float* Wih0 = (const float*)d_in[3];
    const float* Whh0 = (const float*)d_in[4];
    const float* bih0 = (const float*)d_in[5];
    const float* bhh0 = (const float*)d_in[6];
    const float* Wih1 = (const float*)d_in[7];
    const float* Whh1 = (const float*)d_in[8];
    const float* bih1 = (const float*)d_in[9];
    const float* bhh1 = (const float*)d_in[10];
    const float* Wout = (const float*)d_in[11];
    const float* bout = (const float*)d_in[12];
    float* out = (float*)d_out;

    float *bufA, *bufB;
    cudaGetSymbolAddress((void**)&bufA, g_bufA);
    cudaGetSymbolAddress((void**)&bufB, g_bufB);

    cudaFuncSetAttribute(rnn_rec, cudaFuncAttributeMaxDynamicSharedMemorySize, REC_SMEM);

    dim3 blk(256);
    // 1) xw0 = emb[tok] @ Wih0^T + (bih0 + bhh0)   -> bufA
    gemm_kernel<<<dim3(H_ / 128, M_ / 128), blk, GEMM_SMEM>>>(
        emb, tok, Wih0, bih0, bhh0, bufA, H_);
    // 2) layer-0 recurrence: y0 -> bufB, h0_final -> out[OUT_HID]
    rnn_rec<<<NB, 256, REC_SMEM>>>(bufA, Whh0, hid, bufB, out + OUT_HID);
    // 3) xw1 = y0 @ Wih1^T + (bih1 + bhh1)         -> bufA
    gemm_kernel<<<dim3(H_ / 128, M_ / 128), blk, GEMM_SMEM>>>(
        bufB, nullptr, Wih1, bih1, bhh1, bufA, H_);
    // 4) layer-1 recurrence: y1 -> bufB, h1_final -> out[OUT_HID + B*H]
    rnn_rec<<<NB, 256, REC_SMEM>>>(bufA, Whh1, hid + B_ * H_, bufB,
                                   out + OUT_HID + (size_t)B_ * H_);
    // 5) output_prob = y1 @ Wout^T + bout          -> out[0..M*V)
    gemm_kernel<<<dim3(V_ / 128, M_ / 128), blk, GEMM_SMEM>>>(
        bufB, nullptr, Wout, bout, nullptr, out, V_);
    // 6) last_output = rows (b*T + T-1) of output_prob
    copy_last<<<(B_ * V_) / 256, 256>>>(out, out + OUT_LAST);
}

// round 3
// speedup vs baseline: 1.7514x; 1.7514x over previous
#include <cuda_runtime.h>
#include <cuda_bf16.h>
#include <cstdint>

// Problem dims
#define V_ 32000
#define E_ 1024
#define H_ 1024
#define B_ 32
#define T_ 128
#define M_ (B_ * T_)          // 4096

// Output layout in d_out
#define OUT_HID  ((size_t)M_ * V_)
#define OUT_LAST (OUT_HID + 2ULL * B_ * H_)

typedef unsigned long long ull;
typedef __nv_bfloat16 bf16;

// ---------------- scratch (device globals) ----------------
__device__ float g_bufA[M_ * H_];
__device__ float g_bufB[M_ * H_];
__device__ float g_hbuf[2][B_ * H_];
__device__ ull   g_acnt = 0;
__device__ ull   g_gen  = 0;

__device__ bf16 g_Whi[(size_t)V_ * H_];
__device__ bf16 g_Wlo[(size_t)V_ * H_];
__device__ bf16 g_Ahi[(size_t)M_ * H_];
__device__ bf16 g_Alo[(size_t)M_ * H_];
__device__ bf16 g_Phi[(size_t)H_ * H_];
__device__ bf16 g_Plo[(size_t)H_ * H_];

// ---------------- helpers ----------------
__device__ __forceinline__ void ffma2(ull& c, ull a, ull b) {
    asm("fma.rn.f32x2 %0, %1, %2, %0;" : "+l"(c) : "l"(a), "l"(b));
}
__device__ __forceinline__ float2 unpack2(ull v) {
    float2 r; asm("mov.b64 {%0, %1}, %2;" : "=f"(r.x), "=f"(r.y) : "l"(v)); return r;
}
__device__ __forceinline__ uint32_t smem_u32(const void* p) {
    uint32_t a;
    asm("{ .reg .u64 t; cvta.to.shared.u64 t, %1; cvt.u32.u64 %0, t; }" : "=r"(a) : "l"(p));
    return a;
}
__device__ __forceinline__ void cpa16(uint32_t d, const void* s) {
    asm volatile("cp.async.cg.shared.global [%0], [%1], 16;" :: "r"(d), "l"(s));
}
#define CP_COMMIT() asm volatile("cp.async.commit_group;" ::: "memory")
#define CP_WAIT1()  asm volatile("cp.async.wait_group 1;" ::: "memory")
#define CP_WAIT0()  asm volatile("cp.async.wait_group 0;" ::: "memory")

__device__ __forceinline__ void ldsm4(uint32_t& r0, uint32_t& r1, uint32_t& r2, uint32_t& r3,
                                      uint32_t addr) {
    asm volatile("ldmatrix.sync.aligned.m8n8.x4.shared.b16 {%0,%1,%2,%3}, [%4];"
                 : "=r"(r0), "=r"(r1), "=r"(r2), "=r"(r3) : "r"(addr));
}
__device__ __forceinline__ void mma16816(float* c, const uint32_t* a, const uint32_t* b) {
    asm volatile(
        "mma.sync.aligned.m16n8k16.row.col.f32.bf16.bf16.f32 "
        "{%0,%1,%2,%3}, {%4,%5,%6,%7}, {%8,%9}, {%0,%1,%2,%3};"
        : "+f"(c[0]), "+f"(c[1]), "+f"(c[2]), "+f"(c[3])
        : "r"(a[0]), "r"(a[1]), "r"(a[2]), "r"(a[3]), "r"(b[0]), "r"(b[1]));
}

// ============================================================================
// Split kernels: fp32 -> (hi, lo) bf16
// ============================================================================
__global__ void split_kernel(const float* __restrict__ src,
                             bf16* __restrict__ hi, bf16* __restrict__ lo)
{
    size_t i = ((size_t)blockIdx.x * 256 + threadIdx.x) * 4;
    float4 v = *(const float4*)(src + i);
    union { bf16 h[4]; uint2 u; } H, L;
    float vv[4] = {v.x, v.y, v.z, v.w};
    #pragma unroll
    for (int j = 0; j < 4; j++) {
        bf16 h = __float2bfloat16_rn(vv[j]);
        H.h[j] = h;
        L.h[j] = __float2bfloat16_rn(vv[j] - __bfloat162float(h));
    }
    *(uint2*)(hi + i) = H.u;
    *(uint2*)(lo + i) = L.u;
}

__global__ void split_gather(const float* __restrict__ emb, const int* __restrict__ tok,
                             bf16* __restrict__ hi, bf16* __restrict__ lo)
{
    int m = blockIdx.x;
    int row = tok[m];
    size_t s = (size_t)row * H_ + threadIdx.x * 4;
    size_t d = (size_t)m * H_ + threadIdx.x * 4;
    float4 v = *(const float4*)(emb + s);
    union { bf16 h[4]; uint2 u; } H, L;
    float vv[4] = {v.x, v.y, v.z, v.w};
    #pragma unroll
    for (int j = 0; j < 4; j++) {
        bf16 h = __float2bfloat16_rn(vv[j]);
        H.h[j] = h;
        L.h[j] = __float2bfloat16_rn(vv[j] - __bfloat162float(h));
    }
    *(uint2*)(hi + d) = H.u;
    *(uint2*)(lo + d) = L.u;
}

// ============================================================================
// mma.sync split-bf16 GEMM: C[m][n] = sum_k A[m][k]*B[n][k] + bias
// Tile 128x128, K-chunk 32, 3-stage cp.async, 8 warps (2x4), warp tile 64x32.
// ============================================================================
#define NCC 32                 // 1024 / 32 chunks
#define TILE_B 8192u           // one operand tile: 128 rows x 32 k x 2B
#define STG_B  (4u * TILE_B)   // Ahi, Alo, Bhi, Blo = 32 KB
#define NSTG 3
#define MMA_SMEM (NSTG * STG_B)

// swizzled smem address: rows of 64 B (32 bf16), 4 x 16B chunks per row
__device__ __forceinline__ uint32_t sw_addr(uint32_t tile, int row, int chunk) {
    return tile + (uint32_t)row * 64u + (uint32_t)((chunk ^ ((row >> 1) & 3)) * 16);
}

__device__ __forceinline__ void load_chunk(
    uint32_t stg, const bf16* __restrict__ Ahi, const bf16* __restrict__ Alo,
    const bf16* __restrict__ Bhi, const bf16* __restrict__ Blo,
    int m0, int n0, int kc, int tid)
{
    const int koff = kc * 32;
    #pragma unroll
    for (int j = 0; j < 8; j++) {
        int idx = tid + j * 256;
        int tile = idx >> 9;            // 0:Ahi 1:Alo 2:Bhi 3:Blo
        int rem = idx & 511;
        int r = rem >> 2, c = rem & 3;
        const bf16* src;
        int grow;
        if (tile == 0)      { src = Ahi; grow = m0 + r; }
        else if (tile == 1) { src = Alo; grow = m0 + r; }
        else if (tile == 2) { src = Bhi; grow = n0 + r; }
        else                { src = Blo; grow = n0 + r; }
        cpa16(sw_addr(stg + (uint32_t)tile * TILE_B, r, c),
              src + (size_t)grow * H_ + koff + c * 8);
    }
    CP_COMMIT();
}

__global__ void __launch_bounds__(256, 1) mma_gemm(
    const bf16* __restrict__ Ahi, const bf16* __restrict__ Alo,
    const bf16* __restrict__ Bhi, const bf16* __restrict__ Blo,
    const float* __restrict__ bias1, const float* __restrict__ bias2,
    float* __restrict__ C, int ldn, float* __restrict__ lastout)
{
    extern __shared__ char smc[];
    const uint32_t smb = smem_u32(smc);
    const int tid = threadIdx.x;
    const int wid = tid >> 5, lid = tid & 31;
    const int wm = wid >> 2, wn = wid & 3;      // warp tile: 64 m x 32 n
    const int m0 = blockIdx.x * 128;
    const int n0 = blockIdx.y * 128;

    float acc[4][4][4];
    #pragma unroll
    for (int i = 0; i < 4; i++)
        #pragma unroll
        for (int j = 0; j < 4; j++)
            #pragma unroll
            for (int q = 0; q < 4; q++) acc[i][j][q] = 0.0f;

    // ldmatrix lane addressing components
    const int l7 = lid & 7;
    const int lb8 = (lid >> 3) & 1;
    const int lb16 = lid >> 4;
    const int lm = lid >> 3;                    // 0..3, B x4 matrix index

    load_chunk(smb,             Ahi, Alo, Bhi, Blo, m0, n0, 0, tid);
    load_chunk(smb + STG_B,     Ahi, Alo, Bhi, Blo, m0, n0, 1, tid);

    for (int i = 0; i < NCC; i++) {
        if (i < NCC - 1) { CP_WAIT1(); } else { CP_WAIT0(); }
        __syncthreads();

        const uint32_t stg = smb + (uint32_t)(i % NSTG) * STG_B;
        const uint32_t tAhi = stg, tAlo = stg + TILE_B;
        const uint32_t tBhi = stg + 2 * TILE_B, tBlo = stg + 3 * TILE_B;

        #pragma unroll
        for (int ks = 0; ks < 2; ks++) {
            uint32_t ahi[4][4], alo[4][4], bhi[4][2], blo[4][2];
            const int ach = ks * 2 + lb16;
            #pragma unroll
            for (int mi = 0; mi < 4; mi++) {
                int row = wm * 64 + mi * 16 + l7 + lb8 * 8;
                ldsm4(ahi[mi][0], ahi[mi][1], ahi[mi][2], ahi[mi][3], sw_addr(tAhi, row, ach));
                ldsm4(alo[mi][0], alo[mi][1], alo[mi][2], alo[mi][3], sw_addr(tAlo, row, ach));
            }
            const int bch = ks * 2 + (lm & 1);
            #pragma unroll
            for (int p = 0; p < 2; p++) {
                int row = wn * 32 + p * 16 + l7 + ((lm >= 2) ? 8 : 0);
                uint32_t r0, r1, r2, r3;
                ldsm4(r0, r1, r2, r3, sw_addr(tBhi, row, bch));
                bhi[2*p][0] = r0; bhi[2*p][1] = r1; bhi[2*p+1][0] = r2; bhi[2*p+1][1] = r3;
                ldsm4(r0, r1, r2, r3, sw_addr(tBlo, row, bch));
                blo[2*p][0] = r0; blo[2*p][1] = r1; blo[2*p+1][0] = r2; blo[2*p+1][1] = r3;
            }
            #pragma unroll
            for (int mi = 0; mi < 4; mi++)
                #pragma unroll
                for (int nj = 0; nj < 4; nj++) {
                    mma16816(acc[mi][nj], ahi[mi], bhi[nj]);
                    mma16816(acc[mi][nj], alo[mi], bhi[nj]);
                    mma16816(acc[mi][nj], ahi[mi], blo[nj]);
                }
        }

        if (i + 2 < NCC)
            load_chunk(smb + (uint32_t)((i + 2) % NSTG) * STG_B,
                       Ahi, Alo, Bhi, Blo, m0, n0, i + 2, tid);
    }

    // epilogue
    const int gid = lid >> 2, tig = lid & 3;
    #pragma unroll
    for (int nj = 0; nj < 4; nj++) {
        const int col = n0 + wn * 32 + nj * 8 + tig * 2;
        float2 bv;
        bv.x = bias1[col]; bv.y = bias1[col + 1];
        if (bias2) { bv.x += bias2[col]; bv.y += bias2[col + 1]; }
        #pragma unroll
        for (int mi = 0; mi < 4; mi++) {
            const int r0 = m0 + wm * 64 + mi * 16 + gid;
            float2 v0 = {acc[mi][nj][0] + bv.x, acc[mi][nj][1] + bv.y};
            float2 v1 = {acc[mi][nj][2] + bv.x, acc[mi][nj][3] + bv.y};
            *(float2*)(C + (size_t)r0 * ldn + col) = v0;
            *(float2*)(C + (size_t)(r0 + 8) * ldn + col) = v1;
            if (lastout && ((r0 + 8) & 127) == 127)     // global row b*T + 127
                *(float2*)(lastout + (size_t)blockIdx.x * ldn + col) = v1;
        }
    }
}

// ============================================================================
// Persistent recurrence: h = tanh(xw[:,t,:] + h @ Whh^T)
// ============================================================================
#define NB 128
#define HS 1028
#define REC_SMEM ((32 * HS + 8 * 33 + 2) * 4)

__device__ __forceinline__ void gridbar() {
    __syncthreads();
    if (threadIdx.x == 0) {
        __threadfence();
        ull a = atomicAdd(&g_acnt, 1ULL) + 1ULL;
        ull tgt = (a + NB - 1) / NB;
        if (a == tgt * NB) {
            atomicExch(&g_gen, tgt);
        } else {
            while (*((volatile ull*)&g_gen) < tgt) { __nanosleep(64); }
        }
        __threadfence();
    }
    __syncthreads();
}

__global__ void __launch_bounds__(256, 1) rnn_rec(
    const float* __restrict__ xw, const float* __restrict__ Whh,
    const float* __restrict__ hinit, float* __restrict__ y, float* __restrict__ hfin)
{
    extern __shared__ float smf[];
    float* h_s  = smf;
    float* hn_s = smf + 32 * HS;

    const int tid = threadIdx.x;
    const int blk = blockIdx.x;
    const int b  = tid & 31;
    const int il = tid >> 5;
    const int i  = blk * 8 + il;
    const int bb = tid >> 3;
    const int io = tid & 7;
    const int iw = blk * 8 + io;

    g_hbuf[0][bb * H_ + iw] = hinit[bb * H_ + iw];
    gridbar();

    const float* wrow = Whh + (size_t)i * H_;

    for (int t = 0; t < T_; t++) {
        const float* hcur = g_hbuf[t & 1];
        #pragma unroll
        for (int r = 0; r < 32; r++)
            *(float4*)&h_s[r * HS + tid * 4] = *(const float4*)&hcur[r * H_ + tid * 4];
        __syncthreads();

        ull a0 = 0, a1 = 0, a2 = 0, a3 = 0;
        const float* hb = h_s + b * HS;
        #pragma unroll 4
        for (int j = 0; j < H_; j += 8) {
            ulonglong2 hv0 = *(const ulonglong2*)(hb + j);
            ulonglong2 hv1 = *(const ulonglong2*)(hb + j + 4);
            ulonglong2 wv0 = *(const ulonglong2*)(wrow + j);
            ulonglong2 wv1 = *(const ulonglong2*)(wrow + j + 4);
            ffma2(a0, hv0.x, wv0.x);
            ffma2(a1, hv0.y, wv0.y);
            ffma2(a2, hv1.x, wv1.x);
            ffma2(a3, hv1.y, wv1.y);
        }
        float2 f0 = unpack2(a0), f1 = unpack2(a1), f2 = unpack2(a2), f3 = unpack2(a3);
        float dot = ((f0.x + f0.y) + (f1.x + f1.y)) + ((f2.x + f2.y) + (f3.x + f3.y));
        float hv = tanhf(dot + xw[((size_t)b * T_ + t) * H_ + i]);

        hn_s[il * 33 + b] = hv;
        __syncthreads();

        float v = hn_s[io * 33 + bb];
        g_hbuf[(t + 1) & 1][bb * H_ + iw] = v;
        y[((size_t)bb * T_ + t) * H_ + iw] = v;
        if (t == T_ - 1) hfin[bb * H_ + iw] = v;

        gridbar();
    }
}

// ============================================================================
extern "C" void kernel_launch(void* const* d_in, const int* in_sizes, int n_in,
                              void* d_out, int out_size)
{
    const int*   tok  = (const int*)  d_in[0];
    const float* hid  = (const float*)d_in[1];
    const float* emb  = (const float*)d_in[2];
    const float* Wih0 = (const float*)d_in[3];
    const float* Whh0 = (const float*)d_in[4];
    const float* bih0 = (const float*)d_in[5];
    const float* bhh0 = (const float*)d_in[6];
    const float* Wih1 = (const float*)d_in[7];
    const float* Whh1 = (const float*)d_in[8];
    const float* bih1 = (const float*)d_in[9];
    const float* bhh1 = (const float*)d_in[10];
    const float* Wout = (const float*)d_in[11];
    const float* bout = (const float*)d_in[12];
    float* out = (float*)d_out;

    float *bufA, *bufB;
    bf16 *Whi, *Wlo, *Ahi, *Alo, *Phi, *Plo;
    cudaGetSymbolAddress((void**)&bufA, g_bufA);
    cudaGetSymbolAddress((void**)&bufB, g_bufB);
    cudaGetSymbolAddress((void**)&Whi, g_Whi);
    cudaGetSymbolAddress((void**)&Wlo, g_Wlo);
    cudaGetSymbolAddress((void**)&Ahi, g_Ahi);
    cudaGetSymbolAddress((void**)&Alo, g_Alo);
    cudaGetSymbolAddress((void**)&Phi, g_Phi);
    cudaGetSymbolAddress((void**)&Plo, g_Plo);

    cudaFuncSetAttribute(mma_gemm, cudaFuncAttributeMaxDynamicSharedMemorySize, MMA_SMEM);
    cudaFuncSetAttribute(rnn_rec, cudaFuncAttributeMaxDynamicSharedMemorySize, REC_SMEM);

    // W_out split (largest)
    split_kernel<<<(size_t)V_ * H_ / 1024, 256>>>(Wout, Whi, Wlo);

    // layer 0
    split_gather<<<M_, 256>>>(emb, tok, Ahi, Alo);
    split_kernel<<<(size_t)H_ * H_ / 1024, 256>>>(Wih0, Phi, Plo);
    mma_gemm<<<dim3(M_ / 128, H_ / 128), 256, MMA_SMEM>>>(
        Ahi, Alo, Phi, Plo, bih0, bhh0, bufA, H_, nullptr);
    rnn_rec<<<NB, 256, REC_SMEM>>>(bufA, Whh0, hid, bufB, out + OUT_HID);

    // layer 1
    split_kernel<<<(size_t)M_ * H_ / 1024, 256>>>(bufB, Ahi, Alo);
    split_kernel<<<(size_t)H_ * H_ / 1024, 256>>>(Wih1, Phi, Plo);
    mma_gemm<<<dim3(M_ / 128, H_ / 128), 256, MMA_SMEM>>>(
        Ahi, Alo, Phi, Plo, bih1, bhh1, bufA, H_, nullptr);
    rnn_rec<<<NB, 256, REC_SMEM>>>(bufA, Whh1, hid + B_ * H_, bufB,
                                   out + OUT_HID + (size_t)B_ * H_);

    // output projection (last_output fused)
    split_kernel<<<(size_t)M_ * H_ / 1024, 256>>>(bufB, Ahi, Alo);
    mma_gemm<<<dim3(M_ / 128, V_ / 128), 256, MMA_SMEM>>>(
        Ahi, Alo, Whi, Wlo, bout, nullptr, out, V_, out + OUT_LAST);
}

// round 6
// speedup vs baseline: 2.3135x; 1.3210x over previous
#include <cuda_runtime.h>
#include <cuda_bf16.h>
#include <cuda_fp16.h>
#include <cstdint>

// Problem dims
#define V_ 32000
#define E_ 1024
#define H_ 1024
#define B_ 32
#define T_ 128
#define M_ (B_ * T_)          // 4096

// Output layout in d_out
#define OUT_HID  ((size_t)M_ * V_)
#define OUT_LAST (OUT_HID + 2ULL * B_ * H_)

typedef unsigned long long ull;
typedef __nv_bfloat16 bf16;

// ---------------- scratch (device globals) ----------------
__device__ float g_bufA[M_ * H_];
__device__ float g_bufB[M_ * H_];
__device__ float g_hbuf[2][B_ * H_];
__device__ ull   g_acnt = 0;
__device__ ull   g_gen  = 0;

__device__ bf16 g_Ahi[(size_t)M_ * H_];      // proj A splits (bf16)
__device__ bf16 g_Alo[(size_t)M_ * H_];
__device__ bf16 g_Phi[(size_t)H_ * H_];      // proj W splits (bf16)
__device__ bf16 g_Plo[(size_t)H_ * H_];
__device__ half g_Wh16[(size_t)V_ * H_];     // W_out fp16 (single)
__device__ half g_Ah16[(size_t)M_ * H_];     // output-A fp16 splits
__device__ half g_Al16[(size_t)M_ * H_];

// ---------------- helpers ----------------
__device__ __forceinline__ void ffma2(ull& c, ull a, ull b) {
    asm("fma.rn.f32x2 %0, %1, %2, %0;" : "+l"(c) : "l"(a), "l"(b));
}
__device__ __forceinline__ float2 unpack2(ull v) {
    float2 r; asm("mov.b64 {%0, %1}, %2;" : "=f"(r.x), "=f"(r.y) : "l"(v)); return r;
}
__device__ __forceinline__ uint32_t smem_u32(const void* p) {
    uint32_t a;
    asm("{ .reg .u64 t; cvta.to.shared.u64 t, %1; cvt.u32.u64 %0, t; }" : "=r"(a) : "l"(p));
    return a;
}
__device__ __forceinline__ void cpa16(uint32_t d, const void* s) {
    asm volatile("cp.async.cg.shared.global [%0], [%1], 16;" :: "r"(d), "l"(s));
}
#define CP_COMMIT() asm volatile("cp.async.commit_group;" ::: "memory")
#define CP_WAIT0()  asm volatile("cp.async.wait_group 0;" ::: "memory")
#define CP_WAIT1()  asm volatile("cp.async.wait_group 1;" ::: "memory")
#define CP_WAIT2()  asm volatile("cp.async.wait_group 2;" ::: "memory")
#define CP_WAIT3()  asm volatile("cp.async.wait_group 3;" ::: "memory")

__device__ __forceinline__ void ldsm4(uint32_t& r0, uint32_t& r1, uint32_t& r2, uint32_t& r3,
                                      uint32_t addr) {
    asm volatile("ldmatrix.sync.aligned.m8n8.x4.shared.b16 {%0,%1,%2,%3}, [%4];"
                 : "=r"(r0), "=r"(r1), "=r"(r2), "=r"(r3) : "r"(addr));
}
__device__ __forceinline__ void mma_bf(float* c, const uint32_t* a, const uint32_t* b) {
    asm volatile(
        "mma.sync.aligned.m16n8k16.row.col.f32.bf16.bf16.f32 "
        "{%0,%1,%2,%3}, {%4,%5,%6,%7}, {%8,%9}, {%0,%1,%2,%3};"
        : "+f"(c[0]), "+f"(c[1]), "+f"(c[2]), "+f"(c[3])
        : "r"(a[0]), "r"(a[1]), "r"(a[2]), "r"(a[3]), "r"(b[0]), "r"(b[1]));
}
__device__ __forceinline__ void mma_fp(float* c, const uint32_t* a, const uint32_t* b) {
    asm volatile(
        "mma.sync.aligned.m16n8k16.row.col.f32.f16.f16.f32 "
        "{%0,%1,%2,%3}, {%4,%5,%6,%7}, {%8,%9}, {%0,%1,%2,%3};"
        : "+f"(c[0]), "+f"(c[1]), "+f"(c[2]), "+f"(c[3])
        : "r"(a[0]), "r"(a[1]), "r"(a[2]), "r"(a[3]), "r"(b[0]), "r"(b[1]));
}

// ============================================================================
// Conversion kernels
// ============================================================================
__global__ void split_bf(const float* __restrict__ src,
                         bf16* __restrict__ hi, bf16* __restrict__ lo)
{
    size_t i = ((size_t)blockIdx.x * 256 + threadIdx.x) * 4;
    float4 v = *(const float4*)(src + i);
    union { bf16 h[4]; uint2 u; } H, L;
    float vv[4] = {v.x, v.y, v.z, v.w};
    #pragma unroll
    for (int j = 0; j < 4; j++) {
        bf16 h = __float2bfloat16_rn(vv[j]);
        H.h[j] = h;
        L.h[j] = __float2bfloat16_rn(vv[j] - __bfloat162float(h));
    }
    *(uint2*)(hi + i) = H.u;
    *(uint2*)(lo + i) = L.u;
}

__global__ void split_gather_bf(const float* __restrict__ emb, const int* __restrict__ tok,
                                bf16* __restrict__ hi, bf16* __restrict__ lo)
{
    int m = blockIdx.x;
    int row = tok[m];
    size_t s = (size_t)row * H_ + threadIdx.x * 4;
    size_t d = (size_t)m * H_ + threadIdx.x * 4;
    float4 v = *(const float4*)(emb + s);
    union { bf16 h[4]; uint2 u; } H, L;
    float vv[4] = {v.x, v.y, v.z, v.w};
    #pragma unroll
    for (int j = 0; j < 4; j++) {
        bf16 h = __float2bfloat16_rn(vv[j]);
        H.h[j] = h;
        L.h[j] = __float2bfloat16_rn(vv[j] - __bfloat162float(h));
    }
    *(uint2*)(hi + d) = H.u;
    *(uint2*)(lo + d) = L.u;
}

__global__ void split_f16(const float* __restrict__ src,
                          half* __restrict__ hi, half* __restrict__ lo)
{
    size_t i = ((size_t)blockIdx.x * 256 + threadIdx.x) * 4;
    float4 v = *(const float4*)(src + i);
    union { half h[4]; uint2 u; } H, L;
    float vv[4] = {v.x, v.y, v.z, v.w};
    #pragma unroll
    for (int j = 0; j < 4; j++) {
        half h = __float2half_rn(vv[j]);
        H.h[j] = h;
        L.h[j] = __float2half_rn(vv[j] - __half2float(h));
    }
    *(uint2*)(hi + i) = H.u;
    *(uint2*)(lo + i) = L.u;
}

__global__ void conv_f16(const float* __restrict__ src, half* __restrict__ dst)
{
    size_t i = ((size_t)blockIdx.x * 256 + threadIdx.x) * 8;
    float4 v0 = *(const float4*)(src + i);
    float4 v1 = *(const float4*)(src + i + 4);
    union { half h[8]; uint4 u; } O;
    O.h[0] = __float2half_rn(v0.x); O.h[1] = __float2half_rn(v0.y);
    O.h[2] = __float2half_rn(v0.z); O.h[3] = __float2half_rn(v0.w);
    O.h[4] = __float2half_rn(v1.x); O.h[5] = __float2half_rn(v1.y);
    O.h[6] = __float2half_rn(v1.z); O.h[7] = __float2half_rn(v1.w);
    *(uint4*)(dst + i) = O.u;
}

// ============================================================================
// Shared GEMM pieces: 128x128 tile, K-chunk 32, row = 64 B of 16-bit elems
// ============================================================================
__device__ __forceinline__ uint32_t sw_addr(uint32_t tile, int row, int chunk) {
    return tile + (uint32_t)row * 64u + (uint32_t)((chunk ^ ((row >> 1) & 3)) * 16);
}
#define TILE_B 8192u
#define NCC 32

// ---------------- bf16 3-term projection GEMM (1 CTA/SM) ----------------
#define STG3_B  (4u * TILE_B)
#define NSTG3 3
#define MMA3_SMEM (NSTG3 * STG3_B)

__device__ __forceinline__ void load_chunk3(
    uint32_t stg, const bf16* __restrict__ Ahi, const bf16* __restrict__ Alo,
    const bf16* __restrict__ Bhi, const bf16* __restrict__ Blo,
    int m0, int n0, int kc, int tid)
{
    const int koff = kc * 32;
    #pragma unroll
    for (int j = 0; j < 8; j++) {
        int idx = tid + j * 256;
        int tile = idx >> 9;
        int rem = idx & 511;
        int r = rem >> 2, c = rem & 3;
        const bf16* src;
        int grow;
        if (tile == 0)      { src = Ahi; grow = m0 + r; }
        else if (tile == 1) { src = Alo; grow = m0 + r; }
        else if (tile == 2) { src = Bhi; grow = n0 + r; }
        else                { src = Blo; grow = n0 + r; }
        cpa16(sw_addr(stg + (uint32_t)tile * TILE_B, r, c),
              src + (size_t)grow * H_ + koff + c * 8);
    }
    CP_COMMIT();
}

__global__ void __launch_bounds__(256, 1) mma_gemm3(
    const bf16* __restrict__ Ahi, const bf16* __restrict__ Alo,
    const bf16* __restrict__ Bhi, const bf16* __restrict__ Blo,
    const float* __restrict__ bias1, const float* __restrict__ bias2,
    float* __restrict__ C, int ldn)
{
    extern __shared__ char smc[];
    const uint32_t smb = smem_u32(smc);
    const int tid = threadIdx.x;
    const int wid = tid >> 5, lid = tid & 31;
    const int wm = wid >> 2, wn = wid & 3;
    const int m0 = blockIdx.x * 128;
    const int n0 = blockIdx.y * 128;

    float acc[4][4][4];
    #pragma unroll
    for (int i = 0; i < 4; i++)
        #pragma unroll
        for (int j = 0; j < 4; j++)
            #pragma unroll
            for (int q = 0; q < 4; q++) acc[i][j][q] = 0.0f;

    const int l7 = lid & 7;
    const int lb8 = (lid >> 3) & 1;
    const int lb16 = lid >> 4;
    const int lm = lid >> 3;

    load_chunk3(smb,          Ahi, Alo, Bhi, Blo, m0, n0, 0, tid);
    load_chunk3(smb + STG3_B, Ahi, Alo, Bhi, Blo, m0, n0, 1, tid);

    for (int i = 0; i < NCC; i++) {
        if (i < NCC - 1) { CP_WAIT1(); } else { CP_WAIT0(); }
        __syncthreads();

        const uint32_t stg = smb + (uint32_t)(i % NSTG3) * STG3_B;
        const uint32_t tAhi = stg, tAlo = stg + TILE_B;
        const uint32_t tBhi = stg + 2 * TILE_B, tBlo = stg + 3 * TILE_B;

        #pragma unroll
        for (int ks = 0; ks < 2; ks++) {
            uint32_t ahi[4][4], alo[4][4], bhi[4][2], blo[4][2];
            const int ach = ks * 2 + lb16;
            #pragma unroll
            for (int mi = 0; mi < 4; mi++) {
                int row = wm * 64 + mi * 16 + l7 + lb8 * 8;
                ldsm4(ahi[mi][0], ahi[mi][1], ahi[mi][2], ahi[mi][3], sw_addr(tAhi, row, ach));
                ldsm4(alo[mi][0], alo[mi][1], alo[mi][2], alo[mi][3], sw_addr(tAlo, row, ach));
            }
            const int bch = ks * 2 + (lm & 1);
            #pragma unroll
            for (int p = 0; p < 2; p++) {
                int row = wn * 32 + p * 16 + l7 + ((lm >= 2) ? 8 : 0);
                uint32_t r0, r1, r2, r3;
                ldsm4(r0, r1, r2, r3, sw_addr(tBhi, row, bch));
                bhi[2*p][0] = r0; bhi[2*p][1] = r1; bhi[2*p+1][0] = r2; bhi[2*p+1][1] = r3;
                ldsm4(r0, r1, r2, r3, sw_addr(tBlo, row, bch));
                blo[2*p][0] = r0; blo[2*p][1] = r1; blo[2*p+1][0] = r2; blo[2*p+1][1] = r3;
            }
            #pragma unroll
            for (int mi = 0; mi < 4; mi++)
                #pragma unroll
                for (int nj = 0; nj < 4; nj++) {
                    mma_bf(acc[mi][nj], ahi[mi], bhi[nj]);
                    mma_bf(acc[mi][nj], alo[mi], bhi[nj]);
                    mma_bf(acc[mi][nj], ahi[mi], blo[nj]);
                }
        }

        if (i + 2 < NCC)
            load_chunk3(smb + (uint32_t)((i + 2) % NSTG3) * STG3_B,
                        Ahi, Alo, Bhi, Blo, m0, n0, i + 2, tid);
    }

    const int gid = lid >> 2, tig = lid & 3;
    #pragma unroll
    for (int nj = 0; nj < 4; nj++) {
        const int col = n0 + wn * 32 + nj * 8 + tig * 2;
        float2 bv;
        bv.x = bias1[col]; bv.y = bias1[col + 1];
        if (bias2) { bv.x += bias2[col]; bv.y += bias2[col + 1]; }
        #pragma unroll
        for (int mi = 0; mi < 4; mi++) {
            const int r0 = m0 + wm * 64 + mi * 16 + gid;
            float2 v0 = {acc[mi][nj][0] + bv.x, acc[mi][nj][1] + bv.y};
            float2 v1 = {acc[mi][nj][2] + bv.x, acc[mi][nj][3] + bv.y};
            *(float2*)(C + (size_t)r0 * ldn + col) = v0;
            *(float2*)(C + (size_t)(r0 + 8) * ldn + col) = v1;
        }
    }
}

// ---------------- fp16 2-term output GEMM (2 CTAs/SM, 4 stages) ----------------
#define STG2_B  (3u * TILE_B)      // Ahi, Alo, Bh = 24 KB
#define NSTG2 4
#define MMA2_SMEM (NSTG2 * STG2_B) // 96 KB

__device__ __forceinline__ void load_chunk2(
    uint32_t stg, const half* __restrict__ Ahi, const half* __restrict__ Alo,
    const half* __restrict__ Bh, int m0, int n0, int kc, int tid)
{
    const int koff = kc * 32;
    #pragma unroll
    for (int j = 0; j < 6; j++) {
        int idx = tid + j * 256;
        int tile = idx >> 9;
        int rem = idx & 511;
        int r = rem >> 2, c = rem & 3;
        const half* src;
        int grow;
        if (tile == 0)      { src = Ahi; grow = m0 + r; }
        else if (tile == 1) { src = Alo; grow = m0 + r; }
        else                { src = Bh;  grow = n0 + r; }
        cpa16(sw_addr(stg + (uint32_t)tile * TILE_B, r, c),
              src + (size_t)grow * H_ + koff + c * 8);
    }
    CP_COMMIT();
}

__global__ void __launch_bounds__(256, 2) mma_gemm2(
    const half* __restrict__ Ahi, const half* __restrict__ Alo,
    const half* __restrict__ Bh, const float* __restrict__ bias1,
    float* __restrict__ C, int ldn, float* __restrict__ lastout)
{
    extern __shared__ char smc[];
    const uint32_t smb = smem_u32(smc);
    const int tid = threadIdx.x;
    const int wid = tid >> 5, lid = tid & 31;
    const int wm = wid >> 2, wn = wid & 3;
    const int m0 = blockIdx.x * 128;
    const int n0 = blockIdx.y * 128;

    float acc[4][4][4];
    #pragma unroll
    for (int i = 0; i < 4; i++)
        #pragma unroll
        for (int j = 0; j < 4; j++)
            #pragma unroll
            for (int q = 0; q < 4; q++) acc[i][j][q] = 0.0f;

    const int l7 = lid & 7;
    const int lb8 = (lid >> 3) & 1;
    const int lb16 = lid >> 4;
    const int lm = lid >> 3;

    load_chunk2(smb,              Ahi, Alo, Bh, m0, n0, 0, tid);
    load_chunk2(smb + STG2_B,     Ahi, Alo, Bh, m0, n0, 1, tid);
    load_chunk2(smb + 2 * STG2_B, Ahi, Alo, Bh, m0, n0, 2, tid);

    for (int i = 0; i < NCC; i++) {
        if (i + 3 < NCC) {
            load_chunk2(smb + (uint32_t)((i + 3) % NSTG2) * STG2_B,
                        Ahi, Alo, Bh, m0, n0, i + 3, tid);
            CP_WAIT3();
        } else if (i + 2 < NCC) { CP_WAIT2(); }
        else if (i + 1 < NCC)   { CP_WAIT1(); }
        else                    { CP_WAIT0(); }
        __syncthreads();

        const uint32_t stg = smb + (uint32_t)(i % NSTG2) * STG2_B;
        const uint32_t tAhi = stg, tAlo = stg + TILE_B, tBh = stg + 2 * TILE_B;

        #pragma unroll
        for (int ks = 0; ks < 2; ks++) {
            uint32_t a[4][4], bh[4][2];
            const int ach = ks * 2 + lb16;
            const int bch = ks * 2 + (lm & 1);
            #pragma unroll
            for (int p = 0; p < 2; p++) {
                int row = wn * 32 + p * 16 + l7 + ((lm >= 2) ? 8 : 0);
                uint32_t r0, r1, r2, r3;
                ldsm4(r0, r1, r2, r3, sw_addr(tBh, row, bch));
                bh[2*p][0] = r0; bh[2*p][1] = r1; bh[2*p+1][0] = r2; bh[2*p+1][1] = r3;
            }
            // hi pass
            #pragma unroll
            for (int mi = 0; mi < 4; mi++) {
                int row = wm * 64 + mi * 16 + l7 + lb8 * 8;
                ldsm4(a[mi][0], a[mi][1], a[mi][2], a[mi][3], sw_addr(tAhi, row, ach));
            }
            #pragma unroll
            for (int mi = 0; mi < 4; mi++)
                #pragma unroll
                for (int nj = 0; nj < 4; nj++)
                    mma_fp(acc[mi][nj], a[mi], bh[nj]);
            // lo pass (reuses a[] registers)
            #pragma unroll
            for (int mi = 0; mi < 4; mi++) {
                int row = wm * 64 + mi * 16 + l7 + lb8 * 8;
                ldsm4(a[mi][0], a[mi][1], a[mi][2], a[mi][3], sw_addr(tAlo, row, ach));
            }
            #pragma unroll
            for (int mi = 0; mi < 4; mi++)
                #pragma unroll
                for (int nj = 0; nj < 4; nj++)
                    mma_fp(acc[mi][nj], a[mi], bh[nj]);
        }
        __syncthreads();
    }

    const int gid = lid >> 2, tig = lid & 3;
    #pragma unroll
    for (int nj = 0; nj < 4; nj++) {
        const int col = n0 + wn * 32 + nj * 8 + tig * 2;
        float2 bv;
        bv.x = bias1[col]; bv.y = bias1[col + 1];
        #pragma unroll
        for (int mi = 0; mi < 4; mi++) {
            const int r0 = m0 + wm * 64 + mi * 16 + gid;
            float2 v0 = {acc[mi][nj][0] + bv.x, acc[mi][nj][1] + bv.y};
            float2 v1 = {acc[mi][nj][2] + bv.x, acc[mi][nj][3] + bv.y};
            *(float2*)(C + (size_t)r0 * ldn + col) = v0;
            *(float2*)(C + (size_t)(r0 + 8) * ldn + col) = v1;
            if (lastout && ((r0 + 8) & 127) == 127)
                *(float2*)(lastout + (size_t)blockIdx.x * ldn + col) = v1;
        }
    }
}

// ============================================================================
// Recurrence v2 (FIXED h staging): h = tanh(xw[:,t,:] + h @ Whh^T)
// Block owns 8 i-rows (W staged once in smem). Warp w -> b in [w*4,w*4+4),
// lane = i_loc*4 + bs. h[32][1024] staged per step via cp.async in 2 halves:
// 4096 16B-chunks per half, 16 per thread.
// ============================================================================
#define NB 128
#define HPAD 1028
#define REC_SMEM ((32 * HPAD + 8 * HPAD + 8 * 33 + 4) * 4)

__device__ __forceinline__ void gridbar() {
    __syncthreads();
    if (threadIdx.x == 0) {
        __threadfence();
        ull a = atomicAdd(&g_acnt, 1ULL) + 1ULL;
        ull tgt = (a + NB - 1) / NB;
        if (a == tgt * NB) {
            atomicExch(&g_gen, tgt);
        } else {
            while (*((volatile ull*)&g_gen) < tgt) { __nanosleep(64); }
        }
        __threadfence();
    }
    __syncthreads();
}

__global__ void __launch_bounds__(256, 1) rnn_rec2(
    const float* __restrict__ xw, const float* __restrict__ Whh,
    const float* __restrict__ hinit, float* __restrict__ y, float* __restrict__ hfin)
{
    extern __shared__ float smf[];
    float* h_s  = smf;                         // [32][HPAD]
    float* w_s  = smf + 32 * HPAD;             // [8][HPAD]
    float* hv_s = smf + 40 * HPAD;             // [8][33]

    const int tid = threadIdx.x;
    const int blk = blockIdx.x;
    const int wrp = tid >> 5, lane = tid & 31;
    const int i_loc = lane >> 2;
    const int b = wrp * 4 + (lane & 3);
    const int i = blk * 8 + i_loc;

    // stage W rows for this block (once): 8 rows x 1024 floats = 2048 float4
    #pragma unroll
    for (int q = 0; q < 8; q++) {
        int fi = tid + q * 256;
        int r = fi >> 8, c = (fi & 255) * 4;
        *(float4*)&w_s[r * HPAD + c] =
            *(const float4*)&Whh[(size_t)(blk * 8 + r) * H_ + c];
    }
    g_hbuf[0][blk * 256 + tid] = hinit[blk * 256 + tid];
    gridbar();

    const uint32_t h_sb = smem_u32(h_s);
    const float* wrow = w_s + i_loc * HPAD;
    const float* hrow = h_s + b * HPAD;

    for (int t = 0; t < T_; t++) {
        const float* hcur = g_hbuf[t & 1];
        // half A: j in [0,512): 32 rows x 128 chunks = 4096 chunks of 16B
        #pragma unroll
        for (int q = 0; q < 16; q++) {
            int ci = tid + q * 256;            // [0,4096)
            int r = ci >> 7, c = ci & 127;
            cpa16(h_sb + (uint32_t)(r * HPAD * 4 + c * 16), hcur + r * H_ + c * 4);
        }
        CP_COMMIT();
        // half B: j in [512,1024)
        #pragma unroll
        for (int q = 0; q < 16; q++) {
            int ci = tid + q * 256;
            int r = ci >> 7, c = 128 + (ci & 127);
            cpa16(h_sb + (uint32_t)(r * HPAD * 4 + c * 16), hcur + r * H_ + c * 4);
        }
        CP_COMMIT();

        float xv = xw[((size_t)b * T_ + t) * H_ + i];

        ull a0 = 0, a1 = 0;
        CP_WAIT1();
        __syncthreads();
        #pragma unroll 8
        for (int j = 0; j < 512; j += 4) {
            ulonglong2 hq = *(const ulonglong2*)(hrow + j);
            ulonglong2 wq = *(const ulonglong2*)(wrow + j);
            ffma2(a0, hq.x, wq.x);
            ffma2(a1, hq.y, wq.y);
        }
        CP_WAIT0();
        __syncthreads();
        #pragma unroll 8
        for (int j = 512; j < 1024; j += 4) {
            ulonglong2 hq = *(const ulonglong2*)(hrow + j);
            ulonglong2 wq = *(const ulonglong2*)(wrow + j);
            ffma2(a0, hq.x, wq.x);
            ffma2(a1, hq.y, wq.y);
        }
        float2 f0 = unpack2(a0), f1 = unpack2(a1);
        float dot = (f0.x + f0.y) + (f1.x + f1.y);
        float hv = tanhf(dot + xv);

        hv_s[i_loc * 33 + b] = hv;
        __syncthreads();

        {
            int bb = tid >> 3, io = tid & 7;
            float v = hv_s[io * 33 + bb];
            g_hbuf[(t + 1) & 1][bb * H_ + blk * 8 + io] = v;
            y[((size_t)bb * T_ + t) * H_ + blk * 8 + io] = v;
            if (t == T_ - 1) hfin[bb * H_ + blk * 8 + io] = v;
        }
        gridbar();
    }
}

// ============================================================================
extern "C" void kernel_launch(void* const* d_in, const int* in_sizes, int n_in,
                              void* d_out, int out_size)
{
    const int*   tok  = (const int*)  d_in[0];
    const float* hid  = (const float*)d_in[1];
    const float* emb  = (const float*)d_in[2];
    const float* Wih0 = (const float*)d_in[3];
    const float* Whh0 = (const float*)d_in[4];
    const float* bih0 = (const float*)d_in[5];
    const float* bhh0 = (const float*)d_in[6];
    const float* Wih1 = (const float*)d_in[7];
    const float* Whh1 = (const float*)d_in[8];
    const float* bih1 = (const float*)d_in[9];
    const float* bhh1 = (const float*)d_in[10];
    const float* Wout = (const float*)d_in[11];
    const float* bout = (const float*)d_in[12];
    float* out = (float*)d_out;

    float *bufA, *bufB;
    bf16 *Ahi, *Alo, *Phi, *Plo;
    half *Wh16, *Ah16, *Al16;
    cudaGetSymbolAddress((void**)&bufA, g_bufA);
    cudaGetSymbolAddress((void**)&bufB, g_bufB);
    cudaGetSymbolAddress((void**)&Ahi, g_Ahi);
    cudaGetSymbolAddress((void**)&Alo, g_Alo);
    cudaGetSymbolAddress((void**)&Phi, g_Phi);
    cudaGetSymbolAddress((void**)&Plo, g_Plo);
    cudaGetSymbolAddress((void**)&Wh16, g_Wh16);
    cudaGetSymbolAddress((void**)&Ah16, g_Ah16);
    cudaGetSymbolAddress((void**)&Al16, g_Al16);

    cudaFuncSetAttribute(mma_gemm3, cudaFuncAttributeMaxDynamicSharedMemorySize, MMA3_SMEM);
    cudaFuncSetAttribute(mma_gemm2, cudaFuncAttributeMaxDynamicSharedMemorySize, MMA2_SMEM);
    cudaFuncSetAttribute(rnn_rec2, cudaFuncAttributeMaxDynamicSharedMemorySize, REC_SMEM);

    // W_out -> fp16 (single term)
    conv_f16<<<(int)((size_t)V_ * H_ / 2048), 256>>>(Wout, Wh16);

    // layer 0
    split_gather_bf<<<M_, 256>>>(emb, tok, Ahi, Alo);
    split_bf<<<(int)((size_t)H_ * H_ / 1024), 256>>>(Wih0, Phi, Plo);
    mma_gemm3<<<dim3(M_ / 128, H_ / 128), 256, MMA3_SMEM>>>(
        Ahi, Alo, Phi, Plo, bih0, bhh0, bufA, H_);
    rnn_rec2<<<NB, 256, REC_SMEM>>>(bufA, Whh0, hid, bufB, out + OUT_HID);

    // layer 1
    split_bf<<<(int)((size_t)M_ * H_ / 1024), 256>>>(bufB, Ahi, Alo);
    split_bf<<<(int)((size_t)H_ * H_ / 1024), 256>>>(Wih1, Phi, Plo);
    mma_gemm3<<<dim3(M_ / 128, H_ / 128), 256, MMA3_SMEM>>>(
        Ahi, Alo, Phi, Plo, bih1, bhh1, bufA, H_);
    rnn_rec2<<<NB, 256, REC_SMEM>>>(bufA, Whh1, hid + B_ * H_, bufB,
                                    out + OUT_HID + (size_t)B_ * H_);

    // output projection: fp16 2-term, last_output fused
    split_f16<<<(int)((size_t)M_ * H_ / 1024), 256>>>(bufB, Ah16, Al16);
    mma_gemm2<<<dim3(M_ / 128, V_ / 128), 256, MMA2_SMEM>>>(
        Ah16, Al16, Wh16, bout, out, V_, out + OUT_LAST);
}

// round 11
// speedup vs baseline: 2.6401x; 1.1412x over previous
#include <cuda_runtime.h>
#include <cuda_bf16.h>
#include <cuda_fp16.h>
#include <cstdint>

// Problem dims
#define V_ 32000
#define E_ 1024
#define H_ 1024
#define B_ 32
#define T_ 128
#define M_ (B_ * T_)          // 4096

// Output layout in d_out
#define OUT_HID  ((size_t)M_ * V_)
#define OUT_LAST (OUT_HID + 2ULL * B_ * H_)

typedef unsigned long long ull;
typedef __nv_bfloat16 bf16;

// ---------------- scratch (device globals) ----------------
__device__ float g_bufA[M_ * H_];
__device__ float g_bufB[M_ * H_];
__device__ float g_hbuf[2][B_ * H_];
__device__ ull   g_acnt = 0;
__device__ ull   g_gen  = 0;

__device__ bf16 g_Ahi[(size_t)M_ * H_];      // proj A splits (bf16)
__device__ bf16 g_Alo[(size_t)M_ * H_];
__device__ bf16 g_Phi[(size_t)H_ * H_];      // proj W splits (bf16)
__device__ bf16 g_Plo[(size_t)H_ * H_];
__device__ half g_Wh16[(size_t)V_ * H_];     // W_out fp16
__device__ half g_Ah16[(size_t)M_ * H_];     // output-A fp16

// ---------------- helpers ----------------
__device__ __forceinline__ void ffma2(ull& c, ull a, ull b) {
    asm("fma.rn.f32x2 %0, %1, %2, %0;" : "+l"(c) : "l"(a), "l"(b));
}
__device__ __forceinline__ float2 unpack2(ull v) {
    float2 r; asm("mov.b64 {%0, %1}, %2;" : "=f"(r.x), "=f"(r.y) : "l"(v)); return r;
}
__device__ __forceinline__ uint32_t smem_u32(const void* p) {
    uint32_t a;
    asm("{ .reg .u64 t; cvta.to.shared.u64 t, %1; cvt.u32.u64 %0, t; }" : "=r"(a) : "l"(p));
    return a;
}
__device__ __forceinline__ void cpa16(uint32_t d, const void* s) {
    asm volatile("cp.async.cg.shared.global [%0], [%1], 16;" :: "r"(d), "l"(s));
}
#define CP_COMMIT() asm volatile("cp.async.commit_group;" ::: "memory")
#define CP_WAIT0()  asm volatile("cp.async.wait_group 0;" ::: "memory")
#define CP_WAIT1()  asm volatile("cp.async.wait_group 1;" ::: "memory")
#define CP_WAIT2()  asm volatile("cp.async.wait_group 2;" ::: "memory")
#define CP_WAIT3()  asm volatile("cp.async.wait_group 3;" ::: "memory")

__device__ __forceinline__ void ldsm4(uint32_t& r0, uint32_t& r1, uint32_t& r2, uint32_t& r3,
                                      uint32_t addr) {
    asm volatile("ldmatrix.sync.aligned.m8n8.x4.shared.b16 {%0,%1,%2,%3}, [%4];"
                 : "=r"(r0), "=r"(r1), "=r"(r2), "=r"(r3) : "r"(addr));
}
__device__ __forceinline__ void mma_bf(float* c, const uint32_t* a, const uint32_t* b) {
    asm volatile(
        "mma.sync.aligned.m16n8k16.row.col.f32.bf16.bf16.f32 "
        "{%0,%1,%2,%3}, {%4,%5,%6,%7}, {%8,%9}, {%0,%1,%2,%3};"
        : "+f"(c[0]), "+f"(c[1]), "+f"(c[2]), "+f"(c[3])
        : "r"(a[0]), "r"(a[1]), "r"(a[2]), "r"(a[3]), "r"(b[0]), "r"(b[1]));
}
__device__ __forceinline__ void mma_fp(float* c, const uint32_t* a, const uint32_t* b) {
    asm volatile(
        "mma.sync.aligned.m16n8k16.row.col.f32.f16.f16.f32 "
        "{%0,%1,%2,%3}, {%4,%5,%6,%7}, {%8,%9}, {%0,%1,%2,%3};"
        : "+f"(c[0]), "+f"(c[1]), "+f"(c[2]), "+f"(c[3])
        : "r"(a[0]), "r"(a[1]), "r"(a[2]), "r"(a[3]), "r"(b[0]), "r"(b[1]));
}

// ============================================================================
// Conversion kernels
// ============================================================================
__global__ void split_bf(const float* __restrict__ src,
                         bf16* __restrict__ hi, bf16* __restrict__ lo)
{
    size_t i = ((size_t)blockIdx.x * 256 + threadIdx.x) * 4;
    float4 v = *(const float4*)(src + i);
    union { bf16 h[4]; uint2 u; } H, L;
    float vv[4] = {v.x, v.y, v.z, v.w};
    #pragma unroll
    for (int j = 0; j < 4; j++) {
        bf16 h = __float2bfloat16_rn(vv[j]);
        H.h[j] = h;
        L.h[j] = __float2bfloat16_rn(vv[j] - __bfloat162float(h));
    }
    *(uint2*)(hi + i) = H.u;
    *(uint2*)(lo + i) = L.u;
}

__global__ void split_gather_bf(const float* __restrict__ emb, const int* __restrict__ tok,
                                bf16* __restrict__ hi, bf16* __restrict__ lo)
{
    int m = blockIdx.x;
    int row = tok[m];
    size_t s = (size_t)row * H_ + threadIdx.x * 4;
    size_t d = (size_t)m * H_ + threadIdx.x * 4;
    float4 v = *(const float4*)(emb + s);
    union { bf16 h[4]; uint2 u; } H, L;
    float vv[4] = {v.x, v.y, v.z, v.w};
    #pragma unroll
    for (int j = 0; j < 4; j++) {
        bf16 h = __float2bfloat16_rn(vv[j]);
        H.h[j] = h;
        L.h[j] = __float2bfloat16_rn(vv[j] - __bfloat162float(h));
    }
    *(uint2*)(hi + d) = H.u;
    *(uint2*)(lo + d) = L.u;
}

__global__ void conv_f16(const float* __restrict__ src, half* __restrict__ dst)
{
    size_t i = ((size_t)blockIdx.x * 256 + threadIdx.x) * 8;
    float4 v0 = *(const float4*)(src + i);
    float4 v1 = *(const float4*)(src + i + 4);
    union { half h[8]; uint4 u; } O;
    O.h[0] = __float2half_rn(v0.x); O.h[1] = __float2half_rn(v0.y);
    O.h[2] = __float2half_rn(v0.z); O.h[3] = __float2half_rn(v0.w);
    O.h[4] = __float2half_rn(v1.x); O.h[5] = __float2half_rn(v1.y);
    O.h[6] = __float2half_rn(v1.z); O.h[7] = __float2half_rn(v1.w);
    *(uint4*)(dst + i) = O.u;
}

// ============================================================================
// Shared GEMM pieces: 128x128 tile, K-chunk 32, row = 64 B of 16-bit elems
// ============================================================================
__device__ __forceinline__ uint32_t sw_addr(uint32_t tile, int row, int chunk) {
    return tile + (uint32_t)row * 64u + (uint32_t)((chunk ^ ((row >> 1) & 3)) * 16);
}
#define TILE_B 8192u
#define NCC 32

// ---------------- bf16 3-term projection GEMM (1 CTA/SM) ----------------
#define STG3_B  (4u * TILE_B)
#define NSTG3 3
#define MMA3_SMEM (NSTG3 * STG3_B)

__device__ __forceinline__ void load_chunk3(
    uint32_t stg, const bf16* __restrict__ Ahi, const bf16* __restrict__ Alo,
    const bf16* __restrict__ Bhi, const bf16* __restrict__ Blo,
    int m0, int n0, int kc, int tid)
{
    const int koff = kc * 32;
    #pragma unroll
    for (int j = 0; j < 8; j++) {
        int idx = tid + j * 256;
        int tile = idx >> 9;
        int rem = idx & 511;
        int r = rem >> 2, c = rem & 3;
        const bf16* src;
        int grow;
        if (tile == 0)      { src = Ahi; grow = m0 + r; }
        else if (tile == 1) { src = Alo; grow = m0 + r; }
        else if (tile == 2) { src = Bhi; grow = n0 + r; }
        else                { src = Blo; grow = n0 + r; }
        cpa16(sw_addr(stg + (uint32_t)tile * TILE_B, r, c),
              src + (size_t)grow * H_ + koff + c * 8);
    }
    CP_COMMIT();
}

__global__ void __launch_bounds__(256, 1) mma_gemm3(
    const bf16* __restrict__ Ahi, const bf16* __restrict__ Alo,
    const bf16* __restrict__ Bhi, const bf16* __restrict__ Blo,
    const float* __restrict__ bias1, const float* __restrict__ bias2,
    float* __restrict__ C, int ldn)
{
    extern __shared__ char smc[];
    const uint32_t smb = smem_u32(smc);
    const int tid = threadIdx.x;
    const int wid = tid >> 5, lid = tid & 31;
    const int wm = wid >> 2, wn = wid & 3;
    const int m0 = blockIdx.x * 128;
    const int n0 = blockIdx.y * 128;

    float acc[4][4][4];
    #pragma unroll
    for (int i = 0; i < 4; i++)
        #pragma unroll
        for (int j = 0; j < 4; j++)
            #pragma unroll
            for (int q = 0; q < 4; q++) acc[i][j][q] = 0.0f;

    const int l7 = lid & 7;
    const int lb8 = (lid >> 3) & 1;
    const int lb16 = lid >> 4;
    const int lm = lid >> 3;

    load_chunk3(smb,          Ahi, Alo, Bhi, Blo, m0, n0, 0, tid);
    load_chunk3(smb + STG3_B, Ahi, Alo, Bhi, Blo, m0, n0, 1, tid);

    for (int i = 0; i < NCC; i++) {
        if (i < NCC - 1) { CP_WAIT1(); } else { CP_WAIT0(); }
        __syncthreads();

        const uint32_t stg = smb + (uint32_t)(i % NSTG3) * STG3_B;
        const uint32_t tAhi = stg, tAlo = stg + TILE_B;
        const uint32_t tBhi = stg + 2 * TILE_B, tBlo = stg + 3 * TILE_B;

        #pragma unroll
        for (int ks = 0; ks < 2; ks++) {
            uint32_t ahi[4][4], alo[4][4], bhi[4][2], blo[4][2];
            const int ach = ks * 2 + lb16;
            #pragma unroll
            for (int mi = 0; mi < 4; mi++) {
                int row = wm * 64 + mi * 16 + l7 + lb8 * 8;
                ldsm4(ahi[mi][0], ahi[mi][1], ahi[mi][2], ahi[mi][3], sw_addr(tAhi, row, ach));
                ldsm4(alo[mi][0], alo[mi][1], alo[mi][2], alo[mi][3], sw_addr(tAlo, row, ach));
            }
            const int bch = ks * 2 + (lm & 1);
            #pragma unroll
            for (int p = 0; p < 2; p++) {
                int row = wn * 32 + p * 16 + l7 + ((lm >= 2) ? 8 : 0);
                uint32_t r0, r1, r2, r3;
                ldsm4(r0, r1, r2, r3, sw_addr(tBhi, row, bch));
                bhi[2*p][0] = r0; bhi[2*p][1] = r1; bhi[2*p+1][0] = r2; bhi[2*p+1][1] = r3;
                ldsm4(r0, r1, r2, r3, sw_addr(tBlo, row, bch));
                blo[2*p][0] = r0; blo[2*p][1] = r1; blo[2*p+1][0] = r2; blo[2*p+1][1] = r3;
            }
            #pragma unroll
            for (int mi = 0; mi < 4; mi++)
                #pragma unroll
                for (int nj = 0; nj < 4; nj++) {
                    mma_bf(acc[mi][nj], ahi[mi], bhi[nj]);
                    mma_bf(acc[mi][nj], alo[mi], bhi[nj]);
                    mma_bf(acc[mi][nj], ahi[mi], blo[nj]);
                }
        }

        if (i + 2 < NCC)
            load_chunk3(smb + (uint32_t)((i + 2) % NSTG3) * STG3_B,
                        Ahi, Alo, Bhi, Blo, m0, n0, i + 2, tid);
    }

    const int gid = lid >> 2, tig = lid & 3;
    #pragma unroll
    for (int nj = 0; nj < 4; nj++) {
        const int col = n0 + wn * 32 + nj * 8 + tig * 2;
        float2 bv;
        bv.x = bias1[col]; bv.y = bias1[col + 1];
        if (bias2) { bv.x += bias2[col]; bv.y += bias2[col + 1]; }
        #pragma unroll
        for (int mi = 0; mi < 4; mi++) {
            const int r0 = m0 + wm * 64 + mi * 16 + gid;
            float2 v0 = {acc[mi][nj][0] + bv.x, acc[mi][nj][1] + bv.y};
            float2 v1 = {acc[mi][nj][2] + bv.x, acc[mi][nj][3] + bv.y};
            *(float2*)(C + (size_t)r0 * ldn + col) = v0;
            *(float2*)(C + (size_t)(r0 + 8) * ldn + col) = v1;
        }
    }
}

// ---------------- fp16 single-term output GEMM (2 CTAs/SM, 4 stages) ----------
// Pipeline control flow is IDENTICAL to the R6-passing mma_gemm2 (prefetch i+3,
// then WAIT3/2/1/0, sync, compute, sync) — only the A-lo pass is removed.
#define STG1_B  (2u * TILE_B)      // Ah, Bh = 16 KB
#define NSTG1 4
#define MMA1_SMEM (NSTG1 * STG1_B) // 64 KB

__device__ __forceinline__ void load_chunk1(
    uint32_t stg, const half* __restrict__ Ah, const half* __restrict__ Bh,
    int m0, int n0, int kc, int tid)
{
    const int koff = kc * 32;
    #pragma unroll
    for (int j = 0; j < 4; j++) {
        int idx = tid + j * 256;
        int tile = idx >> 9;               // 0:Ah 1:Bh
        int rem = idx & 511;
        int r = rem >> 2, c = rem & 3;
        const half* src = tile ? Bh : Ah;
        int grow = (tile ? n0 : m0) + r;
        cpa16(sw_addr(stg + (uint32_t)tile * TILE_B, r, c),
              src + (size_t)grow * H_ + koff + c * 8);
    }
    CP_COMMIT();
}

__global__ void __launch_bounds__(256, 2) mma_gemm1(
    const half* __restrict__ Ah, const half* __restrict__ Bh,
    const float* __restrict__ bias1,
    float* __restrict__ C, int ldn, float* __restrict__ lastout)
{
    extern __shared__ char smc[];
    const uint32_t smb = smem_u32(smc);
    const int tid = threadIdx.x;
    const int wid = tid >> 5, lid = tid & 31;
    const int wm = wid >> 2, wn = wid & 3;
    const int m0 = blockIdx.x * 128;
    const int n0 = blockIdx.y * 128;

    float acc[4][4][4];
    #pragma unroll
    for (int i = 0; i < 4; i++)
        #pragma unroll
        for (int j = 0; j < 4; j++)
            #pragma unroll
            for (int q = 0; q < 4; q++) acc[i][j][q] = 0.0f;

    const int l7 = lid & 7;
    const int lb8 = (lid >> 3) & 1;
    const int lb16 = lid >> 4;
    const int lm = lid >> 3;

    // prologue: chunks 0..2 into stages 0..2 (same as R6 mma_gemm2)
    load_chunk1(smb,              Ah, Bh, m0, n0, 0, tid);
    load_chunk1(smb + STG1_B,     Ah, Bh, m0, n0, 1, tid);
    load_chunk1(smb + 2 * STG1_B, Ah, Bh, m0, n0, 2, tid);

    for (int i = 0; i < NCC; i++) {
        if (i + 3 < NCC) {
            load_chunk1(smb + (uint32_t)((i + 3) % NSTG1) * STG1_B,
                        Ah, Bh, m0, n0, i + 3, tid);
            CP_WAIT3();
        } else if (i + 2 < NCC) { CP_WAIT2(); }
        else if (i + 1 < NCC)   { CP_WAIT1(); }
        else                    { CP_WAIT0(); }
        __syncthreads();

        const uint32_t stg = smb + (uint32_t)(i % NSTG1) * STG1_B;
        const uint32_t tAh = stg, tBh = stg + TILE_B;

        #pragma unroll
        for (int ks = 0; ks < 2; ks++) {
            uint32_t a[4][4], bh[4][2];
            const int ach = ks * 2 + lb16;
            const int bch = ks * 2 + (lm & 1);
            #pragma unroll
            for (int p = 0; p < 2; p++) {
                int row = wn * 32 + p * 16 + l7 + ((lm >= 2) ? 8 : 0);
                uint32_t r0, r1, r2, r3;
                ldsm4(r0, r1, r2, r3, sw_addr(tBh, row, bch));
                bh[2*p][0] = r0; bh[2*p][1] = r1; bh[2*p+1][0] = r2; bh[2*p+1][1] = r3;
            }
            #pragma unroll
            for (int mi = 0; mi < 4; mi++) {
                int row = wm * 64 + mi * 16 + l7 + lb8 * 8;
                ldsm4(a[mi][0], a[mi][1], a[mi][2], a[mi][3], sw_addr(tAh, row, ach));
            }
            #pragma unroll
            for (int mi = 0; mi < 4; mi++)
                #pragma unroll
                for (int nj = 0; nj < 4; nj++)
                    mma_fp(acc[mi][nj], a[mi], bh[nj]);
        }
        __syncthreads();
    }

    const int gid = lid >> 2, tig = lid & 3;
    #pragma unroll
    for (int nj = 0; nj < 4; nj++) {
        const int col = n0 + wn * 32 + nj * 8 + tig * 2;
        float2 bv;
        bv.x = bias1[col]; bv.y = bias1[col + 1];
        #pragma unroll
        for (int mi = 0; mi < 4; mi++) {
            const int r0 = m0 + wm * 64 + mi * 16 + gid;
            float2 v0 = {acc[mi][nj][0] + bv.x, acc[mi][nj][1] + bv.y};
            float2 v1 = {acc[mi][nj][2] + bv.x, acc[mi][nj][3] + bv.y};
            *(float2*)(C + (size_t)r0 * ldn + col) = v0;
            *(float2*)(C + (size_t)(r0 + 8) * ldn + col) = v1;
            if (lastout && ((r0 + 8) & 127) == 127)
                *(float2*)(lastout + (size_t)blockIdx.x * ldn + col) = v1;
        }
    }
}

// ============================================================================
// Recurrence v2: h = tanh(xw[:,t,:] + h @ Whh^T)   (unchanged — passed R6)
// ============================================================================
#define NB 128
#define HPAD 1028
#define REC_SMEM ((32 * HPAD + 8 * HPAD + 8 * 33 + 4) * 4)

__device__ __forceinline__ void gridbar() {
    __syncthreads();
    if (threadIdx.x == 0) {
        __threadfence();
        ull a = atomicAdd(&g_acnt, 1ULL) + 1ULL;
        ull tgt = (a + NB - 1) / NB;
        if (a == tgt * NB) {
            atomicExch(&g_gen, tgt);
        } else {
            while (*((volatile ull*)&g_gen) < tgt) { __nanosleep(64); }
        }
        __threadfence();
    }
    __syncthreads();
}

__global__ void __launch_bounds__(256, 1) rnn_rec2(
    const float* __restrict__ xw, const float* __restrict__ Whh,
    const float* __restrict__ hinit, float* __restrict__ y, float* __restrict__ hfin)
{
    extern __shared__ float smf[];
    float* h_s  = smf;                         // [32][HPAD]
    float* w_s  = smf + 32 * HPAD;             // [8][HPAD]
    float* hv_s = smf + 40 * HPAD;             // [8][33]

    const int tid = threadIdx.x;
    const int blk = blockIdx.x;
    const int wrp = tid >> 5, lane = tid & 31;
    const int i_loc = lane >> 2;
    const int b = wrp * 4 + (lane & 3);
    const int i = blk * 8 + i_loc;

    #pragma unroll
    for (int q = 0; q < 8; q++) {
        int fi = tid + q * 256;
        int r = fi >> 8, c = (fi & 255) * 4;
        *(float4*)&w_s[r * HPAD + c] =
            *(const float4*)&Whh[(size_t)(blk * 8 + r) * H_ + c];
    }
    g_hbuf[0][blk * 256 + tid] = hinit[blk * 256 + tid];
    gridbar();

    const uint32_t h_sb = smem_u32(h_s);
    const float* wrow = w_s + i_loc * HPAD;
    const float* hrow = h_s + b * HPAD;

    for (int t = 0; t < T_; t++) {
        const float* hcur = g_hbuf[t & 1];
        #pragma unroll
        for (int q = 0; q < 16; q++) {
            int ci = tid + q * 256;
            int r = ci >> 7, c = ci & 127;
            cpa16(h_sb + (uint32_t)(r * HPAD * 4 + c * 16), hcur + r * H_ + c * 4);
        }
        CP_COMMIT();
        #pragma unroll
        for (int q = 0; q < 16; q++) {
            int ci = tid + q * 256;
            int r = ci >> 7, c = 128 + (ci & 127);
            cpa16(h_sb + (uint32_t)(r * HPAD * 4 + c * 16), hcur + r * H_ + c * 4);
        }
        CP_COMMIT();

        float xv = xw[((size_t)b * T_ + t) * H_ + i];

        ull a0 = 0, a1 = 0;
        CP_WAIT1();
        __syncthreads();
        #pragma unroll 8
        for (int j = 0; j < 512; j += 4) {
            ulonglong2 hq = *(const ulonglong2*)(hrow + j);
            ulonglong2 wq = *(const ulonglong2*)(wrow + j);
            ffma2(a0, hq.x, wq.x);
            ffma2(a1, hq.y, wq.y);
        }
        CP_WAIT0();
        __syncthreads();
        #pragma unroll 8
        for (int j = 512; j < 1024; j += 4) {
            ulonglong2 hq = *(const ulonglong2*)(hrow + j);
            ulonglong2 wq = *(const ulonglong2*)(wrow + j);
            ffma2(a0, hq.x, wq.x);
            ffma2(a1, hq.y, wq.y);
        }
        float2 f0 = unpack2(a0), f1 = unpack2(a1);
        float dot = (f0.x + f0.y) + (f1.x + f1.y);
        float hv = tanhf(dot + xv);

        hv_s[i_loc * 33 + b] = hv;
        __syncthreads();

        {
            int bb = tid >> 3, io = tid & 7;
            float v = hv_s[io * 33 + bb];
            g_hbuf[(t + 1) & 1][bb * H_ + blk * 8 + io] = v;
            y[((size_t)bb * T_ + t) * H_ + blk * 8 + io] = v;
            if (t == T_ - 1) hfin[bb * H_ + blk * 8 + io] = v;
        }
        gridbar();
    }
}

// ============================================================================
extern "C" void kernel_launch(void* const* d_in, const int* in_sizes, int n_in,
                              void* d_out, int out_size)
{
    const int*   tok  = (const int*)  d_in[0];
    const float* hid  = (const float*)d_in[1];
    const float* emb  = (const float*)d_in[2];
    const float* Wih0 = (const float*)d_in[3];
    const float* Whh0 = (const float*)d_in[4];
    const float* bih0 = (const float*)d_in[5];
    const float* bhh0 = (const float*)d_in[6];
    const float* Wih1 = (const float*)d_in[7];
    const float* Whh1 = (const float*)d_in[8];
    const float* bih1 = (const float*)d_in[9];
    const float* bhh1 = (const float*)d_in[10];
    const float* Wout = (const float*)d_in[11];
    const float* bout = (const float*)d_in[12];
    float* out = (float*)d_out;

    float *bufA, *bufB;
    bf16 *Ahi, *Alo, *Phi, *Plo;
    half *Wh16, *Ah16;
    cudaGetSymbolAddress((void**)&bufA, g_bufA);
    cudaGetSymbolAddress((void**)&bufB, g_bufB);
    cudaGetSymbolAddress((void**)&Ahi, g_Ahi);
    cudaGetSymbolAddress((void**)&Alo, g_Alo);
    cudaGetSymbolAddress((void**)&Phi, g_Phi);
    cudaGetSymbolAddress((void**)&Plo, g_Plo);
    cudaGetSymbolAddress((void**)&Wh16, g_Wh16);
    cudaGetSymbolAddress((void**)&Ah16, g_Ah16);

    cudaFuncSetAttribute(mma_gemm3, cudaFuncAttributeMaxDynamicSharedMemorySize, MMA3_SMEM);
    cudaFuncSetAttribute(mma_gemm1, cudaFuncAttributeMaxDynamicSharedMemorySize, MMA1_SMEM);
    cudaFuncSetAttribute(rnn_rec2, cudaFuncAttributeMaxDynamicSharedMemorySize, REC_SMEM);

    // W_out -> fp16
    conv_f16<<<(int)((size_t)V_ * H_ / 2048), 256>>>(Wout, Wh16);

    // layer 0
    split_gather_bf<<<M_, 256>>>(emb, tok, Ahi, Alo);
    split_bf<<<(int)((size_t)H_ * H_ / 1024), 256>>>(Wih0, Phi, Plo);
    mma_gemm3<<<dim3(M_ / 128, H_ / 128), 256, MMA3_SMEM>>>(
        Ahi, Alo, Phi, Plo, bih0, bhh0, bufA, H_);
    rnn_rec2<<<NB, 256, REC_SMEM>>>(bufA, Whh0, hid, bufB, out + OUT_HID);

    // layer 1
    split_bf<<<(int)((size_t)M_ * H_ / 1024), 256>>>(bufB, Ahi, Alo);
    split_bf<<<(int)((size_t)H_ * H_ / 1024), 256>>>(Wih1, Phi, Plo);
    mma_gemm3<<<dim3(M_ / 128, H_ / 128), 256, MMA3_SMEM>>>(
        Ahi, Alo, Phi, Plo, bih1, bhh1, bufA, H_);
    rnn_rec2<<<NB, 256, REC_SMEM>>>(bufA, Whh1, hid + B_ * H_, bufB,
                                    out + OUT_HID + (size_t)B_ * H_);

    // output projection: fp16 single-term, last_output fused
    conv_f16<<<(int)((size_t)M_ * H_ / 2048), 256>>>(bufB, Ah16);
    mma_gemm1<<<dim3(M_ / 128, V_ / 128), 256, MMA1_SMEM>>>(
        Ah16, Wh16, bout, out, V_, out + OUT_LAST);
}